// round 4
// baseline (speedup 1.0000x reference)
#include <cuda_runtime.h>

#define BATCH   8
#define NPATCH  784
#define EDIM    384
#define NHEAD   12
#define HDIM    32
#define GRID_S  28

typedef unsigned long long ull;

// -------- scratch (no allocations allowed) --------
__device__ float g_Q[BATCH * NPATCH * EDIM];
__device__ float g_K[BATCH * NPATCH * EDIM];
__device__ float g_V[BATCH * NPATCH * EDIM];
__device__ float g_O[BATCH * NPATCH * EDIM];
__device__ float g_posO[BATCH * NHEAD * NPATCH * HDIM];

// -------- packed f32x2 helpers (sm_103a) --------
__device__ __forceinline__ ull fma2(ull a, ull b, ull c) {
    ull d;
    asm("fma.rn.f32x2 %0, %1, %2, %3;" : "=l"(d) : "l"(a), "l"(b), "l"(c));
    return d;
}
__device__ __forceinline__ ull pack2(float lo, float hi) {
    ull r;
    asm("mov.b64 %0, {%1, %2};" : "=l"(r) : "f"(lo), "f"(hi));
    return r;
}
__device__ __forceinline__ void unpack2(ull v, float& lo, float& hi) {
    asm("mov.b64 {%0, %1}, %2;" : "=f"(lo), "=f"(hi) : "l"(v));
}
__device__ __forceinline__ float ex2f(float x) {
    float y;
    asm("ex2.approx.f32 %0, %1;" : "=f"(y) : "f"(x));
    return y;
}

// =====================================================================
// GEMM: Y[M,384] = X[M,384] @ W^T (+ bias)
// 128x64 tile, 256 threads, 8x4 micro-tile. A stored in smem PRE-DUPLICATED
// as (v,v) 64-bit pairs -> inner loop has ZERO pack MOVs:
// per kk: 4 LDS.128 (A dup) + 1 LDS.128 (B pair) + 16 fma2.
// =====================================================================
#define GTK 16

template <bool HAS_BIAS>
__device__ __forceinline__ void gemm_tile(const float* __restrict__ X,
                                          const float* __restrict__ W,
                                          const float* __restrict__ bias,
                                          float* __restrict__ Y)
{
    __shared__ __align__(16) ull   As2[GTK][128];   // duplicated A: 16 KB
    __shared__ __align__(16) float Bs[GTK][64];     // 4 KB

    const int t    = threadIdx.x;
    const int row0 = blockIdx.x * 128;
    const int col0 = blockIdx.y * 64;
    const int tr   = t >> 4;       // 0..15 -> rows tr*8..tr*8+7
    const int tc   = t & 15;       // 0..15 -> cols tc*4..tc*4+3

    const int arow = t >> 2;          // 0..63
    const int aj4  = (t & 3) << 2;    // k offset 0,4,8,12
    const float* ap0 = X + (size_t)(row0 + arow) * EDIM + aj4;
    const float* ap1 = X + (size_t)(row0 + 64 + arow) * EDIM + aj4;
    const float* bp_ = W + (size_t)(col0 + arow) * EDIM + aj4;

    ull c[8][2];
#pragma unroll
    for (int r = 0; r < 8; r++) { c[r][0] = 0ull; c[r][1] = 0ull; }

    float4 ra0 = *(const float4*)(ap0);
    float4 ra1 = *(const float4*)(ap1);
    float4 rb  = *(const float4*)(bp_);

    for (int s = 0; s < EDIM / GTK; s++) {
        __syncthreads();
        As2[aj4 + 0][arow] = pack2(ra0.x, ra0.x);
        As2[aj4 + 1][arow] = pack2(ra0.y, ra0.y);
        As2[aj4 + 2][arow] = pack2(ra0.z, ra0.z);
        As2[aj4 + 3][arow] = pack2(ra0.w, ra0.w);
        As2[aj4 + 0][64 + arow] = pack2(ra1.x, ra1.x);
        As2[aj4 + 1][64 + arow] = pack2(ra1.y, ra1.y);
        As2[aj4 + 2][64 + arow] = pack2(ra1.z, ra1.z);
        As2[aj4 + 3][64 + arow] = pack2(ra1.w, ra1.w);
        Bs[aj4 + 0][arow] = rb.x; Bs[aj4 + 1][arow] = rb.y;
        Bs[aj4 + 2][arow] = rb.z; Bs[aj4 + 3][arow] = rb.w;
        __syncthreads();

        if (s + 1 < EDIM / GTK) {
            const int ko = (s + 1) * GTK;
            ra0 = *(const float4*)(ap0 + ko);
            ra1 = *(const float4*)(ap1 + ko);
            rb  = *(const float4*)(bp_ + ko);
        }

#pragma unroll
        for (int kk = 0; kk < GTK; kk++) {
            ulonglong2 a01 = *(const ulonglong2*)&As2[kk][tr * 8 + 0];
            ulonglong2 a23 = *(const ulonglong2*)&As2[kk][tr * 8 + 2];
            ulonglong2 a45 = *(const ulonglong2*)&As2[kk][tr * 8 + 4];
            ulonglong2 a67 = *(const ulonglong2*)&As2[kk][tr * 8 + 6];
            ulonglong2 bb  = *(const ulonglong2*)&Bs[kk][tc * 4];
            c[0][0] = fma2(a01.x, bb.x, c[0][0]); c[0][1] = fma2(a01.x, bb.y, c[0][1]);
            c[1][0] = fma2(a01.y, bb.x, c[1][0]); c[1][1] = fma2(a01.y, bb.y, c[1][1]);
            c[2][0] = fma2(a23.x, bb.x, c[2][0]); c[2][1] = fma2(a23.x, bb.y, c[2][1]);
            c[3][0] = fma2(a23.y, bb.x, c[3][0]); c[3][1] = fma2(a23.y, bb.y, c[3][1]);
            c[4][0] = fma2(a45.x, bb.x, c[4][0]); c[4][1] = fma2(a45.x, bb.y, c[4][1]);
            c[5][0] = fma2(a45.y, bb.x, c[5][0]); c[5][1] = fma2(a45.y, bb.y, c[5][1]);
            c[6][0] = fma2(a67.x, bb.x, c[6][0]); c[6][1] = fma2(a67.x, bb.y, c[6][1]);
            c[7][0] = fma2(a67.y, bb.x, c[7][0]); c[7][1] = fma2(a67.y, bb.y, c[7][1]);
        }
    }

    const int j0 = col0 + tc * 4;
    float b0 = 0.f, b1 = 0.f, b2 = 0.f, b3 = 0.f;
    if (HAS_BIAS) {
        float4 bb = *(const float4*)(bias + j0);
        b0 = bb.x; b1 = bb.y; b2 = bb.z; b3 = bb.w;
    }
#pragma unroll
    for (int r = 0; r < 8; r++) {
        const int row = row0 + tr * 8 + r;
        float o0, o1, o2, o3;
        unpack2(c[r][0], o0, o1);
        unpack2(c[r][1], o2, o3);
        float4 o = make_float4(o0 + b0, o1 + b1, o2 + b2, o3 + b3);
        *(float4*)(Y + (size_t)row * EDIM + j0) = o;
    }
}

__global__ __launch_bounds__(256, 3) void qkv_kernel(const float* __restrict__ X,
                                                     const float* __restrict__ Wq,
                                                     const float* __restrict__ Wk,
                                                     const float* __restrict__ Wv)
{
    const float* W;
    float* Y;
    if (blockIdx.z == 0)      { W = Wq; Y = g_Q; }
    else if (blockIdx.z == 1) { W = Wk; Y = g_K; }
    else                      { W = Wv; Y = g_V; }
    gemm_tile<false>(X, W, nullptr, Y);
}

__global__ __launch_bounds__(256, 3) void out_kernel(const float* __restrict__ Wo,
                                                     const float* __restrict__ bo,
                                                     float* __restrict__ Y)
{
    gemm_tile<true>(g_O, Wo, bo, Y);
}

// =====================================================================
// Positional attention output: posO[b,h,n,:] = softmax(pos_logits[h,n,:]) @ V
// Input-independent structure exploited:
//  - W_pos row == 0  -> uniform softmax -> posO = mean_m V  (heads 9..11)
//  - w2 < 0          -> Gaussian stencil: exp(c2*rho^2+dconst) negligible
//                       beyond radius Rf = sqrt((46+|dconst|)/|c2|) (~6 here).
// Truncation < 1e-13 relative. One thread-pair per (b,h,n).
// =====================================================================
__global__ __launch_bounds__(224) void pos_kernel(const float* __restrict__ Wpos,
                                                  const float* __restrict__ bpos)
{
    const int t    = threadIdx.x;
    const int qi   = t >> 1;
    const int half = t & 1;
    const int h = blockIdx.y;
    const int b = blockIdx.z;
    const int n = blockIdx.x * 112 + qi;

    const float LOG2E = 1.4426950408889634f;
    const float w0 = Wpos[h * 3 + 0];
    const float w1 = Wpos[h * 3 + 1];
    const float w2 = Wpos[h * 3 + 2];
    const float bp = bpos[h];

    const float* vbase = g_V + (size_t)b * NPATCH * EDIM + h * HDIM + half * 16;

    ull acc[8];
#pragma unroll
    for (int p = 0; p < 8; p++) acc[p] = 0ull;
    float Z;
    const ull ONE2 = pack2(1.f, 1.f);

    const float mx = fmaxf(fabsf(w0), fmaxf(fabsf(w1), fabsf(w2)));
    if (mx < 1e-12f) {
        // uniform softmax: posO = mean(V)
#pragma unroll 4
        for (int m = 0; m < NPATCH; m++) {
            const ulonglong2* vp = (const ulonglong2*)(vbase + (size_t)m * EDIM);
            ulonglong2 v0 = vp[0], v1 = vp[1], v2 = vp[2], v3 = vp[3];
            acc[0] = fma2(v0.x, ONE2, acc[0]); acc[1] = fma2(v0.y, ONE2, acc[1]);
            acc[2] = fma2(v1.x, ONE2, acc[2]); acc[3] = fma2(v1.y, ONE2, acc[3]);
            acc[4] = fma2(v2.x, ONE2, acc[4]); acc[5] = fma2(v2.y, ONE2, acc[5]);
            acc[6] = fma2(v3.x, ONE2, acc[6]); acc[7] = fma2(v3.y, ONE2, acc[7]);
        }
        Z = (float)NPATCH;
    } else if (fabsf(w2) > 1e-6f) {
        // completed square in log2 domain
        const float inv2   = 0.5f / w2;
        const float c2     = w2 * LOG2E;
        const float dconst = (bp - (w0 * w0 + w1 * w1) * 0.5f * inv2) * LOG2E;
        const float qx = (float)(n % GRID_S) - w0 * inv2;
        const float qy = (float)(n / GRID_S) - w1 * inv2;
        float Rf = 40.f;
        if (c2 < -1e-6f) Rf = sqrtf((46.f + fabsf(dconst)) / (-c2));
        int x0 = max(0, (int)ceilf(qx - Rf));
        int x1 = min(GRID_S - 1, (int)floorf(qx + Rf));
        int y0 = max(0, (int)ceilf(qy - Rf));
        int y1 = min(GRID_S - 1, (int)floorf(qy + Rf));
        Z = 0.f;
        for (int yy = y0; yy <= y1; yy++) {
            const float fdy = (float)yy - qy;
            const float dy2 = fdy * fdy;
            const float* vrow = vbase + (size_t)(yy * GRID_S) * EDIM;
            for (int xx = x0; xx <= x1; xx++) {
                const float fdx = (float)xx - qx;
                const float w = ex2f(fmaf(c2, fmaf(fdx, fdx, dy2), dconst));
                Z += w;
                const ull w2p = pack2(w, w);
                const ulonglong2* vp = (const ulonglong2*)(vrow + (size_t)xx * EDIM);
                ulonglong2 v0 = vp[0], v1 = vp[1], v2_ = vp[2], v3 = vp[3];
                acc[0] = fma2(w2p, v0.x, acc[0]);  acc[1] = fma2(w2p, v0.y, acc[1]);
                acc[2] = fma2(w2p, v1.x, acc[2]);  acc[3] = fma2(w2p, v1.y, acc[3]);
                acc[4] = fma2(w2p, v2_.x, acc[4]); acc[5] = fma2(w2p, v2_.y, acc[5]);
                acc[6] = fma2(w2p, v3.x, acc[6]);  acc[7] = fma2(w2p, v3.y, acc[7]);
            }
        }
    } else {
        // generic fallback: full loop, direct-form logits
        const int qc = n % GRID_S, qr = n / GRID_S;
        Z = 0.f;
        for (int m = 0; m < NPATCH; m++) {
            const float fdx = (float)(m % GRID_S - qc);
            const float fdy = (float)(m / GRID_S - qr);
            const float lg = (fmaf(w0, fdx, fmaf(w1, fdy, w2 * fmaf(fdx, fdx, fdy * fdy))) + bp) * LOG2E;
            const float w = ex2f(lg);
            Z += w;
            const ull w2p = pack2(w, w);
            const ulonglong2* vp = (const ulonglong2*)(vbase + (size_t)m * EDIM);
            ulonglong2 v0 = vp[0], v1 = vp[1], v2_ = vp[2], v3 = vp[3];
            acc[0] = fma2(w2p, v0.x, acc[0]);  acc[1] = fma2(w2p, v0.y, acc[1]);
            acc[2] = fma2(w2p, v1.x, acc[2]);  acc[3] = fma2(w2p, v1.y, acc[3]);
            acc[4] = fma2(w2p, v2_.x, acc[4]); acc[5] = fma2(w2p, v2_.y, acc[5]);
            acc[6] = fma2(w2p, v3.x, acc[6]);  acc[7] = fma2(w2p, v3.y, acc[7]);
        }
    }

    const float inv = 1.f / Z;
    float* op = g_posO + (((size_t)(b * NHEAD + h) * NPATCH + n) * HDIM) + half * 16;
#pragma unroll
    for (int p = 0; p < 8; p++) {
        float a0, a1;
        unpack2(acc[p], a0, a1);
        op[2 * p]     = a0 * inv;
        op[2 * p + 1] = a1 * inv;
    }
}

// =====================================================================
// Patch-only softmax attention + gated blend with precomputed posO.
// 2 threads per query (16 dims each), 256 threads = 128 queries per (b,h).
// K/V streamed in tiles of 112. No max-subtraction needed (logits bounded);
// renormalization is an exact no-op.
// =====================================================================
#define TQ 128
#define TK 112

__global__ __launch_bounds__(256, 4) void attn_kernel(const float* __restrict__ gating)
{
    __shared__ __align__(16) float Ks[TK][HDIM];
    __shared__ __align__(16) float Vs[TK][HDIM];

    const int t    = threadIdx.x;
    const int qi   = t >> 1;
    const int half = t & 1;
    const int h = blockIdx.y;
    const int b = blockIdx.z;
    const int n = blockIdx.x * TQ + qi;
    const bool active = (n < NPATCH);
    const int nc = active ? n : (NPATCH - 1);

    const float LOG2E = 1.4426950408889634f;
    const float sl = 0.28867513459481287f * LOG2E;  // heads^-0.5 * log2(e)

    ull q2[8];
    {
        const float* qp = g_Q + ((size_t)(b * NPATCH + nc) * EDIM) + h * HDIM + half * 16;
#pragma unroll
        for (int p = 0; p < 8; p++)
            q2[p] = pack2(qp[2 * p] * sl, qp[2 * p + 1] * sl);
    }

    ull accP[8];
#pragma unroll
    for (int p = 0; p < 8; p++) accP[p] = 0ull;
    float ZP = 0.f;
    const ull ONE2 = pack2(1.f, 1.f);
    const ull ZERO2 = 0ull;

    for (int m0 = 0; m0 < NPATCH; m0 += TK) {
        __syncthreads();
#pragma unroll
        for (int i = 0; i < 4; i++) {
            const int l = t + i * 256;
            if (l < TK * 8) {
                const int r  = l >> 3;
                const int cc = (l & 7) << 2;
                const size_t base = ((size_t)(b * NPATCH + m0 + r) * EDIM) + h * HDIM + cc;
                *(float4*)&Ks[r][cc] = *(const float4*)(g_K + base);
                *(float4*)&Vs[r][cc] = *(const float4*)(g_V + base);
            }
        }
        __syncthreads();

#pragma unroll 4
        for (int km = 0; km < TK; ++km) {
            const ulonglong2* kp = (const ulonglong2*)&Ks[km][half * 16];
            ulonglong2 k0_ = kp[0], k1_ = kp[1], k2_ = kp[2], k3_ = kp[3];
            ull dA = fma2(q2[0], k0_.x, ZERO2);
            dA = fma2(q2[1], k0_.y, dA);
            dA = fma2(q2[2], k1_.x, dA);
            dA = fma2(q2[3], k1_.y, dA);
            ull dB = fma2(q2[4], k2_.x, ZERO2);
            dB = fma2(q2[5], k2_.y, dB);
            dB = fma2(q2[6], k3_.x, dB);
            dB = fma2(q2[7], k3_.y, dB);
            ull dS = fma2(dA, ONE2, dB);
            float s0, s1;
            unpack2(dS, s0, s1);
            float s = s0 + s1;
            s += __shfl_xor_sync(0xffffffffu, s, 1);   // full 32-dim dot (log2 dom.)

            const float wP = ex2f(s);
            ZP += wP;
            const ull wp2 = pack2(wP, wP);

            const ulonglong2* vp = (const ulonglong2*)&Vs[km][half * 16];
            ulonglong2 v0_ = vp[0], v1_ = vp[1], v2_ = vp[2], v3_ = vp[3];
            accP[0] = fma2(wp2, v0_.x, accP[0]);
            accP[1] = fma2(wp2, v0_.y, accP[1]);
            accP[2] = fma2(wp2, v1_.x, accP[2]);
            accP[3] = fma2(wp2, v1_.y, accP[3]);
            accP[4] = fma2(wp2, v2_.x, accP[4]);
            accP[5] = fma2(wp2, v2_.y, accP[5]);
            accP[6] = fma2(wp2, v3_.x, accP[6]);
            accP[7] = fma2(wp2, v3_.y, accP[7]);
        }
    }

    const float g  = gating[h];
    const float sg = 1.f / (1.f + __expf(-g));
    const float cP = (1.f - sg) / ZP;

    if (active) {
        const float2* pp = (const float2*)(g_posO + (((size_t)(b * NHEAD + h) * NPATCH + n) * HDIM) + half * 16);
        float2* op = (float2*)(g_O + ((size_t)(b * NPATCH + n) * EDIM) + h * HDIM + half * 16);
#pragma unroll
        for (int p = 0; p < 8; p++) {
            float p0, p1;
            unpack2(accP[p], p0, p1);
            const float2 ps = pp[p];
            float2 o;
            o.x = fmaf(cP, p0, sg * ps.x);
            o.y = fmaf(cP, p1, sg * ps.y);
            op[p] = o;
        }
    }
}

// =====================================================================
extern "C" void kernel_launch(void* const* d_in, const int* in_sizes, int n_in,
                              void* d_out, int out_size)
{
    const float* x   = (const float*)d_in[0];
    const float* Wq  = (const float*)d_in[1];
    const float* Wk  = (const float*)d_in[2];
    const float* Wv  = (const float*)d_in[3];
    const float* Wp  = (const float*)d_in[4];
    const float* bp  = (const float*)d_in[5];
    const float* Wo  = (const float*)d_in[6];
    const float* bo  = (const float*)d_in[7];
    const float* gt  = (const float*)d_in[8];
    float* out = (float*)d_out;

    dim3 gq(49, 6, 3);            // 128x64 tiles, 3 GEMMs
    qkv_kernel<<<gq, 256>>>(x, Wq, Wk, Wv);

    dim3 gp(7, NHEAD, BATCH);     // 112 queries/block
    pos_kernel<<<gp, 224>>>(Wp, bp);

    dim3 ga((NPATCH + TQ - 1) / TQ, NHEAD, BATCH);   // (7, 12, 8)
    attn_kernel<<<ga, 256>>>(gt);

    dim3 go(49, 6, 1);
    out_kernel<<<go, 256>>>(Wo, bo, out);
}

// round 5
// speedup vs baseline: 1.0169x; 1.0169x over previous
#include <cuda_runtime.h>

#define BATCH   8
#define NPATCH  784
#define EDIM    384
#define NHEAD   12
#define HDIM    32
#define GRID_S  28

typedef unsigned long long ull;

// -------- scratch (no allocations allowed) --------
__device__ float g_Q[BATCH * NPATCH * EDIM];
__device__ float g_K[BATCH * NPATCH * EDIM];
__device__ float g_V[BATCH * NPATCH * EDIM];
__device__ float g_O[BATCH * NPATCH * EDIM];
__device__ float g_posO[BATCH * NHEAD * NPATCH * HDIM];

// -------- packed f32x2 helpers (sm_103a) --------
__device__ __forceinline__ ull fma2(ull a, ull b, ull c) {
    ull d;
    asm("fma.rn.f32x2 %0, %1, %2, %3;" : "=l"(d) : "l"(a), "l"(b), "l"(c));
    return d;
}
__device__ __forceinline__ ull pack2(float lo, float hi) {
    ull r;
    asm("mov.b64 %0, {%1, %2};" : "=l"(r) : "f"(lo), "f"(hi));
    return r;
}
__device__ __forceinline__ void unpack2(ull v, float& lo, float& hi) {
    asm("mov.b64 {%0, %1}, %2;" : "=f"(lo), "=f"(hi) : "l"(v));
}
__device__ __forceinline__ float ex2f(float x) {
    float y;
    asm("ex2.approx.f32 %0, %1;" : "=f"(y) : "f"(x));
    return y;
}

// =====================================================================
// GEMM: Y[M,384] = X[M,384] @ W^T (+ bias)
// 128x64 tile, 256 threads, 8x4 micro-tile. A stored in smem PRE-DUPLICATED
// as (v,v) 64-bit pairs -> inner loop has ZERO pack MOVs:
// per kk: 4 LDS.128 (A dup) + 1 LDS.128 (B pair) + 16 fma2.
// =====================================================================
#define GTK 16

template <bool HAS_BIAS>
__device__ __forceinline__ void gemm_tile(const float* __restrict__ X,
                                          const float* __restrict__ W,
                                          const float* __restrict__ bias,
                                          float* __restrict__ Y)
{
    __shared__ __align__(16) ull   As2[GTK][128];   // duplicated A: 16 KB
    __shared__ __align__(16) float Bs[GTK][64];     // 4 KB

    const int t    = threadIdx.x;
    const int row0 = blockIdx.x * 128;
    const int col0 = blockIdx.y * 64;
    const int tr   = t >> 4;       // 0..15 -> rows tr*8..tr*8+7
    const int tc   = t & 15;       // 0..15 -> cols tc*4..tc*4+3

    const int arow = t >> 2;          // 0..63
    const int aj4  = (t & 3) << 2;    // k offset 0,4,8,12
    const float* ap0 = X + (size_t)(row0 + arow) * EDIM + aj4;
    const float* ap1 = X + (size_t)(row0 + 64 + arow) * EDIM + aj4;
    const float* bp_ = W + (size_t)(col0 + arow) * EDIM + aj4;

    ull c[8][2];
#pragma unroll
    for (int r = 0; r < 8; r++) { c[r][0] = 0ull; c[r][1] = 0ull; }

    float4 ra0 = *(const float4*)(ap0);
    float4 ra1 = *(const float4*)(ap1);
    float4 rb  = *(const float4*)(bp_);

    for (int s = 0; s < EDIM / GTK; s++) {
        __syncthreads();
        As2[aj4 + 0][arow] = pack2(ra0.x, ra0.x);
        As2[aj4 + 1][arow] = pack2(ra0.y, ra0.y);
        As2[aj4 + 2][arow] = pack2(ra0.z, ra0.z);
        As2[aj4 + 3][arow] = pack2(ra0.w, ra0.w);
        As2[aj4 + 0][64 + arow] = pack2(ra1.x, ra1.x);
        As2[aj4 + 1][64 + arow] = pack2(ra1.y, ra1.y);
        As2[aj4 + 2][64 + arow] = pack2(ra1.z, ra1.z);
        As2[aj4 + 3][64 + arow] = pack2(ra1.w, ra1.w);
        Bs[aj4 + 0][arow] = rb.x; Bs[aj4 + 1][arow] = rb.y;
        Bs[aj4 + 2][arow] = rb.z; Bs[aj4 + 3][arow] = rb.w;
        __syncthreads();

        if (s + 1 < EDIM / GTK) {
            const int ko = (s + 1) * GTK;
            ra0 = *(const float4*)(ap0 + ko);
            ra1 = *(const float4*)(ap1 + ko);
            rb  = *(const float4*)(bp_ + ko);
        }

#pragma unroll
        for (int kk = 0; kk < GTK; kk++) {
            ulonglong2 a01 = *(const ulonglong2*)&As2[kk][tr * 8 + 0];
            ulonglong2 a23 = *(const ulonglong2*)&As2[kk][tr * 8 + 2];
            ulonglong2 a45 = *(const ulonglong2*)&As2[kk][tr * 8 + 4];
            ulonglong2 a67 = *(const ulonglong2*)&As2[kk][tr * 8 + 6];
            ulonglong2 bb  = *(const ulonglong2*)&Bs[kk][tc * 4];
            c[0][0] = fma2(a01.x, bb.x, c[0][0]); c[0][1] = fma2(a01.x, bb.y, c[0][1]);
            c[1][0] = fma2(a01.y, bb.x, c[1][0]); c[1][1] = fma2(a01.y, bb.y, c[1][1]);
            c[2][0] = fma2(a23.x, bb.x, c[2][0]); c[2][1] = fma2(a23.x, bb.y, c[2][1]);
            c[3][0] = fma2(a23.y, bb.x, c[3][0]); c[3][1] = fma2(a23.y, bb.y, c[3][1]);
            c[4][0] = fma2(a45.x, bb.x, c[4][0]); c[4][1] = fma2(a45.x, bb.y, c[4][1]);
            c[5][0] = fma2(a45.y, bb.x, c[5][0]); c[5][1] = fma2(a45.y, bb.y, c[5][1]);
            c[6][0] = fma2(a67.x, bb.x, c[6][0]); c[6][1] = fma2(a67.x, bb.y, c[6][1]);
            c[7][0] = fma2(a67.y, bb.x, c[7][0]); c[7][1] = fma2(a67.y, bb.y, c[7][1]);
        }
    }

    const int j0 = col0 + tc * 4;
    float b0 = 0.f, b1 = 0.f, b2 = 0.f, b3 = 0.f;
    if (HAS_BIAS) {
        float4 bb = *(const float4*)(bias + j0);
        b0 = bb.x; b1 = bb.y; b2 = bb.z; b3 = bb.w;
    }
#pragma unroll
    for (int r = 0; r < 8; r++) {
        const int row = row0 + tr * 8 + r;
        float o0, o1, o2, o3;
        unpack2(c[r][0], o0, o1);
        unpack2(c[r][1], o2, o3);
        float4 o = make_float4(o0 + b0, o1 + b1, o2 + b2, o3 + b3);
        *(float4*)(Y + (size_t)row * EDIM + j0) = o;
    }
}

__global__ __launch_bounds__(256, 3) void qkv_kernel(const float* __restrict__ X,
                                                     const float* __restrict__ Wq,
                                                     const float* __restrict__ Wk,
                                                     const float* __restrict__ Wv)
{
    const float* W;
    float* Y;
    if (blockIdx.z == 0)      { W = Wq; Y = g_Q; }
    else if (blockIdx.z == 1) { W = Wk; Y = g_K; }
    else                      { W = Wv; Y = g_V; }
    gemm_tile<false>(X, W, nullptr, Y);
}

__global__ __launch_bounds__(256, 3) void out_kernel(const float* __restrict__ Wo,
                                                     const float* __restrict__ bo,
                                                     float* __restrict__ Y)
{
    gemm_tile<true>(g_O, Wo, bo, Y);
}

// =====================================================================
// Positional attention output: posO[b,h,n,:] = softmax(pos_logits[h,n,:]) @ V
//  - W_pos row == 0 -> uniform softmax -> posO = mean_m V (heads 9..11)
//  - w2 < 0         -> Gaussian stencil, radius Rf = sqrt((46+|dconst|)/|c2|)
// Truncation < 1e-11 relative.
// =====================================================================
__global__ __launch_bounds__(224) void pos_kernel(const float* __restrict__ Wpos,
                                                  const float* __restrict__ bpos)
{
    const int t    = threadIdx.x;
    const int qi   = t >> 1;
    const int half = t & 1;
    const int h = blockIdx.y;
    const int b = blockIdx.z;
    const int n = blockIdx.x * 112 + qi;

    const float LOG2E = 1.4426950408889634f;
    const float w0 = Wpos[h * 3 + 0];
    const float w1 = Wpos[h * 3 + 1];
    const float w2 = Wpos[h * 3 + 2];
    const float bp = bpos[h];

    const float* vbase = g_V + (size_t)b * NPATCH * EDIM + h * HDIM + half * 16;

    ull acc[8];
#pragma unroll
    for (int p = 0; p < 8; p++) acc[p] = 0ull;
    float Z;
    const ull ONE2 = pack2(1.f, 1.f);

    const float mx = fmaxf(fabsf(w0), fmaxf(fabsf(w1), fabsf(w2)));
    if (mx < 1e-12f) {
#pragma unroll 4
        for (int m = 0; m < NPATCH; m++) {
            const ulonglong2* vp = (const ulonglong2*)(vbase + (size_t)m * EDIM);
            ulonglong2 v0 = vp[0], v1 = vp[1], v2 = vp[2], v3 = vp[3];
            acc[0] = fma2(v0.x, ONE2, acc[0]); acc[1] = fma2(v0.y, ONE2, acc[1]);
            acc[2] = fma2(v1.x, ONE2, acc[2]); acc[3] = fma2(v1.y, ONE2, acc[3]);
            acc[4] = fma2(v2.x, ONE2, acc[4]); acc[5] = fma2(v2.y, ONE2, acc[5]);
            acc[6] = fma2(v3.x, ONE2, acc[6]); acc[7] = fma2(v3.y, ONE2, acc[7]);
        }
        Z = (float)NPATCH;
    } else if (fabsf(w2) > 1e-6f) {
        const float inv2   = 0.5f / w2;
        const float c2     = w2 * LOG2E;
        const float dconst = (bp - (w0 * w0 + w1 * w1) * 0.5f * inv2) * LOG2E;
        const float qx = (float)(n % GRID_S) - w0 * inv2;
        const float qy = (float)(n / GRID_S) - w1 * inv2;
        float Rf = 40.f;
        if (c2 < -1e-6f) Rf = sqrtf((46.f + fabsf(dconst)) / (-c2));
        int x0 = max(0, (int)ceilf(qx - Rf));
        int x1 = min(GRID_S - 1, (int)floorf(qx + Rf));
        int y0 = max(0, (int)ceilf(qy - Rf));
        int y1 = min(GRID_S - 1, (int)floorf(qy + Rf));
        Z = 0.f;
        for (int yy = y0; yy <= y1; yy++) {
            const float fdy = (float)yy - qy;
            const float dy2 = fdy * fdy;
            const float* vrow = vbase + (size_t)(yy * GRID_S) * EDIM;
            for (int xx = x0; xx <= x1; xx++) {
                const float fdx = (float)xx - qx;
                const float w = ex2f(fmaf(c2, fmaf(fdx, fdx, dy2), dconst));
                Z += w;
                const ull w2p = pack2(w, w);
                const ulonglong2* vp = (const ulonglong2*)(vrow + (size_t)xx * EDIM);
                ulonglong2 v0 = vp[0], v1 = vp[1], v2_ = vp[2], v3 = vp[3];
                acc[0] = fma2(w2p, v0.x, acc[0]);  acc[1] = fma2(w2p, v0.y, acc[1]);
                acc[2] = fma2(w2p, v1.x, acc[2]);  acc[3] = fma2(w2p, v1.y, acc[3]);
                acc[4] = fma2(w2p, v2_.x, acc[4]); acc[5] = fma2(w2p, v2_.y, acc[5]);
                acc[6] = fma2(w2p, v3.x, acc[6]);  acc[7] = fma2(w2p, v3.y, acc[7]);
            }
        }
    } else {
        const int qc = n % GRID_S, qr = n / GRID_S;
        Z = 0.f;
        for (int m = 0; m < NPATCH; m++) {
            const float fdx = (float)(m % GRID_S - qc);
            const float fdy = (float)(m / GRID_S - qr);
            const float lg = (fmaf(w0, fdx, fmaf(w1, fdy, w2 * fmaf(fdx, fdx, fdy * fdy))) + bp) * LOG2E;
            const float w = ex2f(lg);
            Z += w;
            const ull w2p = pack2(w, w);
            const ulonglong2* vp = (const ulonglong2*)(vbase + (size_t)m * EDIM);
            ulonglong2 v0 = vp[0], v1 = vp[1], v2_ = vp[2], v3 = vp[3];
            acc[0] = fma2(w2p, v0.x, acc[0]);  acc[1] = fma2(w2p, v0.y, acc[1]);
            acc[2] = fma2(w2p, v1.x, acc[2]);  acc[3] = fma2(w2p, v1.y, acc[3]);
            acc[4] = fma2(w2p, v2_.x, acc[4]); acc[5] = fma2(w2p, v2_.y, acc[5]);
            acc[6] = fma2(w2p, v3.x, acc[6]);  acc[7] = fma2(w2p, v3.y, acc[7]);
        }
    }

    const float inv = 1.f / Z;
    float* op = g_posO + (((size_t)(b * NHEAD + h) * NPATCH + n) * HDIM) + half * 16;
#pragma unroll
    for (int p = 0; p < 8; p++) {
        float a0, a1;
        unpack2(acc[p], a0, a1);
        op[2 * p]     = a0 * inv;
        op[2 * p + 1] = a1 * inv;
    }
}

// =====================================================================
// Patch-only softmax attention + gated blend with precomputed posO.
// 2 threads per query (16 dims each), 256 threads = 128 queries per (b,h).
// NOTE: launch_bounds minBlocks=3 (NOT 4) — 4 forced a 64-reg cap and
// spilled the accumulators into the inner loop (R4 regression).
// =====================================================================
#define TQ 128
#define TK 112

__global__ __launch_bounds__(256, 3) void attn_kernel(const float* __restrict__ gating)
{
    __shared__ __align__(16) float Ks[TK][HDIM];
    __shared__ __align__(16) float Vs[TK][HDIM];

    const int t    = threadIdx.x;
    const int qi   = t >> 1;
    const int half = t & 1;
    const int h = blockIdx.y;
    const int b = blockIdx.z;
    const int n = blockIdx.x * TQ + qi;
    const bool active = (n < NPATCH);
    const int nc = active ? n : (NPATCH - 1);

    const float LOG2E = 1.4426950408889634f;
    const float sl = 0.28867513459481287f * LOG2E;  // heads^-0.5 * log2(e)

    ull q2[8];
    {
        const float* qp = g_Q + ((size_t)(b * NPATCH + nc) * EDIM) + h * HDIM + half * 16;
#pragma unroll
        for (int p = 0; p < 8; p++)
            q2[p] = pack2(qp[2 * p] * sl, qp[2 * p + 1] * sl);
    }

    ull accP[8];
#pragma unroll
    for (int p = 0; p < 8; p++) accP[p] = 0ull;
    float ZP = 0.f;
    const ull ONE2 = pack2(1.f, 1.f);
    const ull ZERO2 = 0ull;

    for (int m0 = 0; m0 < NPATCH; m0 += TK) {
        __syncthreads();
#pragma unroll
        for (int i = 0; i < 4; i++) {
            const int l = t + i * 256;
            if (l < TK * 8) {
                const int r  = l >> 3;
                const int cc = (l & 7) << 2;
                const size_t base = ((size_t)(b * NPATCH + m0 + r) * EDIM) + h * HDIM + cc;
                *(float4*)&Ks[r][cc] = *(const float4*)(g_K + base);
                *(float4*)&Vs[r][cc] = *(const float4*)(g_V + base);
            }
        }
        __syncthreads();

#pragma unroll 4
        for (int km = 0; km < TK; ++km) {
            const ulonglong2* kp = (const ulonglong2*)&Ks[km][half * 16];
            ulonglong2 k0_ = kp[0], k1_ = kp[1], k2_ = kp[2], k3_ = kp[3];
            ull dA = fma2(q2[0], k0_.x, ZERO2);
            dA = fma2(q2[1], k0_.y, dA);
            dA = fma2(q2[2], k1_.x, dA);
            dA = fma2(q2[3], k1_.y, dA);
            ull dB = fma2(q2[4], k2_.x, ZERO2);
            dB = fma2(q2[5], k2_.y, dB);
            dB = fma2(q2[6], k3_.x, dB);
            dB = fma2(q2[7], k3_.y, dB);
            ull dS = fma2(dA, ONE2, dB);
            float s0, s1;
            unpack2(dS, s0, s1);
            float s = s0 + s1;
            s += __shfl_xor_sync(0xffffffffu, s, 1);   // full 32-dim dot (log2 dom.)

            const float wP = ex2f(s);
            ZP += wP;
            const ull wp2 = pack2(wP, wP);

            const ulonglong2* vp = (const ulonglong2*)&Vs[km][half * 16];
            ulonglong2 v0_ = vp[0], v1_ = vp[1], v2_ = vp[2], v3_ = vp[3];
            accP[0] = fma2(wp2, v0_.x, accP[0]);
            accP[1] = fma2(wp2, v0_.y, accP[1]);
            accP[2] = fma2(wp2, v1_.x, accP[2]);
            accP[3] = fma2(wp2, v1_.y, accP[3]);
            accP[4] = fma2(wp2, v2_.x, accP[4]);
            accP[5] = fma2(wp2, v2_.y, accP[5]);
            accP[6] = fma2(wp2, v3_.x, accP[6]);
            accP[7] = fma2(wp2, v3_.y, accP[7]);
        }
    }

    const float g  = gating[h];
    const float sg = 1.f / (1.f + __expf(-g));
    const float cP = (1.f - sg) / ZP;

    if (active) {
        const float2* pp = (const float2*)(g_posO + (((size_t)(b * NHEAD + h) * NPATCH + n) * HDIM) + half * 16);
        float2* op = (float2*)(g_O + ((size_t)(b * NPATCH + n) * EDIM) + h * HDIM + half * 16);
#pragma unroll
        for (int p = 0; p < 8; p++) {
            float p0, p1;
            unpack2(accP[p], p0, p1);
            const float2 ps = pp[p];
            float2 o;
            o.x = fmaf(cP, p0, sg * ps.x);
            o.y = fmaf(cP, p1, sg * ps.y);
            op[p] = o;
        }
    }
}

// =====================================================================
extern "C" void kernel_launch(void* const* d_in, const int* in_sizes, int n_in,
                              void* d_out, int out_size)
{
    const float* x   = (const float*)d_in[0];
    const float* Wq  = (const float*)d_in[1];
    const float* Wk  = (const float*)d_in[2];
    const float* Wv  = (const float*)d_in[3];
    const float* Wp  = (const float*)d_in[4];
    const float* bp  = (const float*)d_in[5];
    const float* Wo  = (const float*)d_in[6];
    const float* bo  = (const float*)d_in[7];
    const float* gt  = (const float*)d_in[8];
    float* out = (float*)d_out;

    dim3 gq(49, 6, 3);            // 128x64 tiles, 3 GEMMs
    qkv_kernel<<<gq, 256>>>(x, Wq, Wk, Wv);

    dim3 gp(7, NHEAD, BATCH);     // 112 queries/block
    pos_kernel<<<gp, 224>>>(Wp, bp);

    dim3 ga((NPATCH + TQ - 1) / TQ, NHEAD, BATCH);   // (7, 12, 8)
    attn_kernel<<<ga, 256>>>(gt);

    dim3 go(49, 6, 1);
    out_kernel<<<go, 256>>>(Wo, bo, out);
}

// round 7
// speedup vs baseline: 1.0536x; 1.0361x over previous
#include <cuda_runtime.h>

#define BATCH   8
#define NPATCH  784
#define EDIM    384
#define NHEAD   12
#define HDIM    32
#define GRID_S  28

typedef unsigned long long ull;

// -------- scratch (no allocations allowed) --------
__device__ float g_Q[BATCH * NPATCH * EDIM];
__device__ float g_K[BATCH * NPATCH * EDIM];
__device__ float g_V[BATCH * NPATCH * EDIM];
__device__ float g_O[BATCH * NPATCH * EDIM];
__device__ float g_posO[BATCH * NHEAD * NPATCH * HDIM];

// -------- packed f32x2 helpers (sm_103a) --------
__device__ __forceinline__ ull fma2(ull a, ull b, ull c) {
    ull d;
    asm("fma.rn.f32x2 %0, %1, %2, %3;" : "=l"(d) : "l"(a), "l"(b), "l"(c));
    return d;
}
__device__ __forceinline__ ull pack2(float lo, float hi) {
    ull r;
    asm("mov.b64 %0, {%1, %2};" : "=l"(r) : "f"(lo), "f"(hi));
    return r;
}
__device__ __forceinline__ void unpack2(ull v, float& lo, float& hi) {
    asm("mov.b64 {%0, %1}, %2;" : "=f"(lo), "=f"(hi) : "l"(v));
}
__device__ __forceinline__ float ex2f(float x) {
    float y;
    asm("ex2.approx.f32 %0, %1;" : "=f"(y) : "f"(x));
    return y;
}

// =====================================================================
// GEMM (R3 version — measured 42.7us/GEMM): Y[M,384] = X[M,384] @ W^T
// 128x64 tile, 256 threads, 8x4 micro-tile, pack-in-loop (dual-issue
// hides the MOVs; de-packed smem variant measured SLOWER in R4/R5).
// =====================================================================
#define GTK 16

template <bool HAS_BIAS>
__device__ __forceinline__ void gemm_tile(const float* __restrict__ X,
                                          const float* __restrict__ W,
                                          const float* __restrict__ bias,
                                          float* __restrict__ Y)
{
    __shared__ __align__(16) float As[GTK][128];
    __shared__ __align__(16) float Bs[GTK][64];

    const int t    = threadIdx.x;
    const int row0 = blockIdx.x * 128;
    const int col0 = blockIdx.y * 64;
    const int tr   = t >> 4;       // 0..15 -> rows tr*8..tr*8+7
    const int tc   = t & 15;       // 0..15 -> cols tc*4..tc*4+3

    const int arow = t >> 2;          // 0..63
    const int aj4  = (t & 3) << 2;    // k offset 0,4,8,12
    const float* ap0 = X + (size_t)(row0 + arow) * EDIM + aj4;
    const float* ap1 = X + (size_t)(row0 + 64 + arow) * EDIM + aj4;
    const float* bp_ = W + (size_t)(col0 + arow) * EDIM + aj4;

    ull c[8][2];
#pragma unroll
    for (int r = 0; r < 8; r++) { c[r][0] = 0ull; c[r][1] = 0ull; }

    float4 ra0 = *(const float4*)(ap0);
    float4 ra1 = *(const float4*)(ap1);
    float4 rb  = *(const float4*)(bp_);

    for (int s = 0; s < EDIM / GTK; s++) {
        __syncthreads();
        As[aj4 + 0][arow] = ra0.x; As[aj4 + 1][arow] = ra0.y;
        As[aj4 + 2][arow] = ra0.z; As[aj4 + 3][arow] = ra0.w;
        As[aj4 + 0][64 + arow] = ra1.x; As[aj4 + 1][64 + arow] = ra1.y;
        As[aj4 + 2][64 + arow] = ra1.z; As[aj4 + 3][64 + arow] = ra1.w;
        Bs[aj4 + 0][arow] = rb.x; Bs[aj4 + 1][arow] = rb.y;
        Bs[aj4 + 2][arow] = rb.z; Bs[aj4 + 3][arow] = rb.w;
        __syncthreads();

        if (s + 1 < EDIM / GTK) {
            const int ko = (s + 1) * GTK;
            ra0 = *(const float4*)(ap0 + ko);
            ra1 = *(const float4*)(ap1 + ko);
            rb  = *(const float4*)(bp_ + ko);
        }

#pragma unroll
        for (int kk = 0; kk < GTK; kk++) {
            float4 a0 = *(const float4*)&As[kk][tr * 8];
            float4 a1 = *(const float4*)&As[kk][tr * 8 + 4];
            ulonglong2 bb = *(const ulonglong2*)&Bs[kk][tc * 4];
            ull A0 = pack2(a0.x, a0.x);
            ull A1 = pack2(a0.y, a0.y);
            ull A2 = pack2(a0.z, a0.z);
            ull A3 = pack2(a0.w, a0.w);
            ull A4 = pack2(a1.x, a1.x);
            ull A5 = pack2(a1.y, a1.y);
            ull A6 = pack2(a1.z, a1.z);
            ull A7 = pack2(a1.w, a1.w);
            c[0][0] = fma2(A0, bb.x, c[0][0]); c[0][1] = fma2(A0, bb.y, c[0][1]);
            c[1][0] = fma2(A1, bb.x, c[1][0]); c[1][1] = fma2(A1, bb.y, c[1][1]);
            c[2][0] = fma2(A2, bb.x, c[2][0]); c[2][1] = fma2(A2, bb.y, c[2][1]);
            c[3][0] = fma2(A3, bb.x, c[3][0]); c[3][1] = fma2(A3, bb.y, c[3][1]);
            c[4][0] = fma2(A4, bb.x, c[4][0]); c[4][1] = fma2(A4, bb.y, c[4][1]);
            c[5][0] = fma2(A5, bb.x, c[5][0]); c[5][1] = fma2(A5, bb.y, c[5][1]);
            c[6][0] = fma2(A6, bb.x, c[6][0]); c[6][1] = fma2(A6, bb.y, c[6][1]);
            c[7][0] = fma2(A7, bb.x, c[7][0]); c[7][1] = fma2(A7, bb.y, c[7][1]);
        }
    }

    const int j0 = col0 + tc * 4;
    float b0 = 0.f, b1 = 0.f, b2 = 0.f, b3 = 0.f;
    if (HAS_BIAS) {
        float4 bb = *(const float4*)(bias + j0);
        b0 = bb.x; b1 = bb.y; b2 = bb.z; b3 = bb.w;
    }
#pragma unroll
    for (int r = 0; r < 8; r++) {
        const int row = row0 + tr * 8 + r;
        float o0, o1, o2, o3;
        unpack2(c[r][0], o0, o1);
        unpack2(c[r][1], o2, o3);
        float4 o = make_float4(o0 + b0, o1 + b1, o2 + b2, o3 + b3);
        *(float4*)(Y + (size_t)row * EDIM + j0) = o;
    }
}

__global__ __launch_bounds__(256, 3) void qkv_kernel(const float* __restrict__ X,
                                                     const float* __restrict__ Wq,
                                                     const float* __restrict__ Wk,
                                                     const float* __restrict__ Wv)
{
    const float* W;
    float* Y;
    if (blockIdx.z == 0)      { W = Wq; Y = g_Q; }
    else if (blockIdx.z == 1) { W = Wk; Y = g_K; }
    else                      { W = Wv; Y = g_V; }
    gemm_tile<false>(X, W, nullptr, Y);
}

__global__ __launch_bounds__(256, 3) void out_kernel(const float* __restrict__ Wo,
                                                     const float* __restrict__ bo,
                                                     float* __restrict__ Y)
{
    gemm_tile<true>(g_O, Wo, bo, Y);
}

// =====================================================================
// Positional attention output: posO[b,h,n,:] = softmax(pos_logits[h,n,:]) @ V
//  - W_pos row == 0 -> uniform softmax -> posO = mean_m V (heads 9..11)
//  - w2 < 0         -> Gaussian stencil, radius Rf = sqrt((46+|dconst|)/|c2|)
// Truncation < 1e-11 relative.
// =====================================================================
__global__ __launch_bounds__(224) void pos_kernel(const float* __restrict__ Wpos,
                                                  const float* __restrict__ bpos)
{
    const int t    = threadIdx.x;
    const int qi   = t >> 1;
    const int half = t & 1;
    const int h = blockIdx.y;
    const int b = blockIdx.z;
    const int n = blockIdx.x * 112 + qi;

    const float LOG2E = 1.4426950408889634f;
    const float w0 = Wpos[h * 3 + 0];
    const float w1 = Wpos[h * 3 + 1];
    const float w2 = Wpos[h * 3 + 2];
    const float bp = bpos[h];

    const float* vbase = g_V + (size_t)b * NPATCH * EDIM + h * HDIM + half * 16;

    ull acc[8];
#pragma unroll
    for (int p = 0; p < 8; p++) acc[p] = 0ull;
    float Z;
    const ull ONE2 = pack2(1.f, 1.f);

    const float mx = fmaxf(fabsf(w0), fmaxf(fabsf(w1), fabsf(w2)));
    if (mx < 1e-12f) {
#pragma unroll 4
        for (int m = 0; m < NPATCH; m++) {
            const ulonglong2* vp = (const ulonglong2*)(vbase + (size_t)m * EDIM);
            ulonglong2 v0 = vp[0], v1 = vp[1], v2 = vp[2], v3 = vp[3];
            acc[0] = fma2(v0.x, ONE2, acc[0]); acc[1] = fma2(v0.y, ONE2, acc[1]);
            acc[2] = fma2(v1.x, ONE2, acc[2]); acc[3] = fma2(v1.y, ONE2, acc[3]);
            acc[4] = fma2(v2.x, ONE2, acc[4]); acc[5] = fma2(v2.y, ONE2, acc[5]);
            acc[6] = fma2(v3.x, ONE2, acc[6]); acc[7] = fma2(v3.y, ONE2, acc[7]);
        }
        Z = (float)NPATCH;
    } else if (fabsf(w2) > 1e-6f) {
        const float inv2   = 0.5f / w2;
        const float c2     = w2 * LOG2E;
        const float dconst = (bp - (w0 * w0 + w1 * w1) * 0.5f * inv2) * LOG2E;
        const float qx = (float)(n % GRID_S) - w0 * inv2;
        const float qy = (float)(n / GRID_S) - w1 * inv2;
        float Rf = 40.f;
        if (c2 < -1e-6f) Rf = sqrtf((46.f + fabsf(dconst)) / (-c2));
        int x0 = max(0, (int)ceilf(qx - Rf));
        int x1 = min(GRID_S - 1, (int)floorf(qx + Rf));
        int y0 = max(0, (int)ceilf(qy - Rf));
        int y1 = min(GRID_S - 1, (int)floorf(qy + Rf));
        Z = 0.f;
        for (int yy = y0; yy <= y1; yy++) {
            const float fdy = (float)yy - qy;
            const float dy2 = fdy * fdy;
            const float* vrow = vbase + (size_t)(yy * GRID_S) * EDIM;
            for (int xx = x0; xx <= x1; xx++) {
                const float fdx = (float)xx - qx;
                const float w = ex2f(fmaf(c2, fmaf(fdx, fdx, dy2), dconst));
                Z += w;
                const ull w2p = pack2(w, w);
                const ulonglong2* vp = (const ulonglong2*)(vrow + (size_t)xx * EDIM);
                ulonglong2 v0 = vp[0], v1 = vp[1], v2_ = vp[2], v3 = vp[3];
                acc[0] = fma2(w2p, v0.x, acc[0]);  acc[1] = fma2(w2p, v0.y, acc[1]);
                acc[2] = fma2(w2p, v1.x, acc[2]);  acc[3] = fma2(w2p, v1.y, acc[3]);
                acc[4] = fma2(w2p, v2_.x, acc[4]); acc[5] = fma2(w2p, v2_.y, acc[5]);
                acc[6] = fma2(w2p, v3.x, acc[6]);  acc[7] = fma2(w2p, v3.y, acc[7]);
            }
        }
    } else {
        const int qc = n % GRID_S, qr = n / GRID_S;
        Z = 0.f;
        for (int m = 0; m < NPATCH; m++) {
            const float fdx = (float)(m % GRID_S - qc);
            const float fdy = (float)(m / GRID_S - qr);
            const float lg = (fmaf(w0, fdx, fmaf(w1, fdy, w2 * fmaf(fdx, fdx, fdy * fdy))) + bp) * LOG2E;
            const float w = ex2f(lg);
            Z += w;
            const ull w2p = pack2(w, w);
            const ulonglong2* vp = (const ulonglong2*)(vbase + (size_t)m * EDIM);
            ulonglong2 v0 = vp[0], v1 = vp[1], v2_ = vp[2], v3 = vp[3];
            acc[0] = fma2(w2p, v0.x, acc[0]);  acc[1] = fma2(w2p, v0.y, acc[1]);
            acc[2] = fma2(w2p, v1.x, acc[2]);  acc[3] = fma2(w2p, v1.y, acc[3]);
            acc[4] = fma2(w2p, v2_.x, acc[4]); acc[5] = fma2(w2p, v2_.y, acc[5]);
            acc[6] = fma2(w2p, v3.x, acc[6]);  acc[7] = fma2(w2p, v3.y, acc[7]);
        }
    }

    const float inv = 1.f / Z;
    float* op = g_posO + (((size_t)(b * NHEAD + h) * NPATCH + n) * HDIM) + half * 16;
#pragma unroll
    for (int p = 0; p < 8; p++) {
        float a0, a1;
        unpack2(acc[p], a0, a1);
        op[2 * p]     = a0 * inv;
        op[2 * p + 1] = a1 * inv;
    }
}

// =====================================================================
// Patch-only softmax attention + gated blend with precomputed posO.
// EXACT R3 loop structure (unroll 2, launch_bounds(256,3)), minus the
// pos-logit math and the second accumulator set.
// =====================================================================
#define TQ 128
#define TK 112

__global__ __launch_bounds__(256, 3) void attn_kernel(const float* __restrict__ gating)
{
    __shared__ __align__(16) float Ks[TK][HDIM];
    __shared__ __align__(16) float Vs[TK][HDIM];

    const int t    = threadIdx.x;
    const int qi   = t >> 1;
    const int half = t & 1;
    const int h = blockIdx.y;
    const int b = blockIdx.z;
    const int n = blockIdx.x * TQ + qi;
    const bool active = (n < NPATCH);
    const int nc = active ? n : (NPATCH - 1);

    const float LOG2E = 1.4426950408889634f;
    const float sl = 0.28867513459481287f * LOG2E;  // heads^-0.5 * log2(e)

    ull q2[8];
    {
        const float* qp = g_Q + ((size_t)(b * NPATCH + nc) * EDIM) + h * HDIM + half * 16;
#pragma unroll
        for (int p = 0; p < 8; p++)
            q2[p] = pack2(qp[2 * p] * sl, qp[2 * p + 1] * sl);
    }

    ull accP[8];
#pragma unroll
    for (int p = 0; p < 8; p++) accP[p] = 0ull;
    float ZP = 0.f;
    const ull ONE2 = pack2(1.f, 1.f);
    const ull ZERO2 = 0ull;

    for (int m0 = 0; m0 < NPATCH; m0 += TK) {
        __syncthreads();
#pragma unroll
        for (int i = 0; i < 4; i++) {
            const int l = t + i * 256;
            if (l < TK * 8) {
                const int r  = l >> 3;
                const int cc = (l & 7) << 2;
                const size_t base = ((size_t)(b * NPATCH + m0 + r) * EDIM) + h * HDIM + cc;
                *(float4*)&Ks[r][cc] = *(const float4*)(g_K + base);
                *(float4*)&Vs[r][cc] = *(const float4*)(g_V + base);
            }
        }
        __syncthreads();

#pragma unroll 2
        for (int km = 0; km < TK; ++km) {
            const ulonglong2* kp = (const ulonglong2*)&Ks[km][half * 16];
            ulonglong2 k0_ = kp[0], k1_ = kp[1], k2_ = kp[2], k3_ = kp[3];
            ull dA = fma2(q2[0], k0_.x, ZERO2);
            dA = fma2(q2[1], k0_.y, dA);
            dA = fma2(q2[2], k1_.x, dA);
            dA = fma2(q2[3], k1_.y, dA);
            ull dB = fma2(q2[4], k2_.x, ZERO2);
            dB = fma2(q2[5], k2_.y, dB);
            dB = fma2(q2[6], k3_.x, dB);
            dB = fma2(q2[7], k3_.y, dB);
            ull dS = fma2(dA, ONE2, dB);
            float s0, s1;
            unpack2(dS, s0, s1);
            float s = s0 + s1;
            s += __shfl_xor_sync(0xffffffffu, s, 1);   // full 32-dim dot (log2 dom.)

            const float wP = ex2f(s);
            ZP += wP;
            const ull wp2 = pack2(wP, wP);

            const ulonglong2* vp = (const ulonglong2*)&Vs[km][half * 16];
            ulonglong2 v0_ = vp[0], v1_ = vp[1], v2_ = vp[2], v3_ = vp[3];
            accP[0] = fma2(wp2, v0_.x, accP[0]);
            accP[1] = fma2(wp2, v0_.y, accP[1]);
            accP[2] = fma2(wp2, v1_.x, accP[2]);
            accP[3] = fma2(wp2, v1_.y, accP[3]);
            accP[4] = fma2(wp2, v2_.x, accP[4]);
            accP[5] = fma2(wp2, v2_.y, accP[5]);
            accP[6] = fma2(wp2, v3_.x, accP[6]);
            accP[7] = fma2(wp2, v3_.y, accP[7]);
        }
    }

    const float g  = gating[h];
    const float sg = 1.f / (1.f + __expf(-g));
    const float cP = (1.f - sg) / ZP;

    if (active) {
        const float2* pp = (const float2*)(g_posO + (((size_t)(b * NHEAD + h) * NPATCH + n) * HDIM) + half * 16);
        float2* op = (float2*)(g_O + ((size_t)(b * NPATCH + n) * EDIM) + h * HDIM + half * 16);
#pragma unroll
        for (int p = 0; p < 8; p++) {
            float p0, p1;
            unpack2(accP[p], p0, p1);
            const float2 ps = pp[p];
            float2 o;
            o.x = fmaf(cP, p0, sg * ps.x);
            o.y = fmaf(cP, p1, sg * ps.y);
            op[p] = o;
        }
    }
}

// =====================================================================
extern "C" void kernel_launch(void* const* d_in, const int* in_sizes, int n_in,
                              void* d_out, int out_size)
{
    const float* x   = (const float*)d_in[0];
    const float* Wq  = (const float*)d_in[1];
    const float* Wk  = (const float*)d_in[2];
    const float* Wv  = (const float*)d_in[3];
    const float* Wp  = (const float*)d_in[4];
    const float* bp  = (const float*)d_in[5];
    const float* Wo  = (const float*)d_in[6];
    const float* bo  = (const float*)d_in[7];
    const float* gt  = (const float*)d_in[8];
    float* out = (float*)d_out;

    dim3 gq(49, 6, 3);            // 128x64 tiles, 3 GEMMs
    qkv_kernel<<<gq, 256>>>(x, Wq, Wk, Wv);

    dim3 gp(7, NHEAD, BATCH);     // 112 queries/block
    pos_kernel<<<gp, 224>>>(Wp, bp);

    dim3 ga((NPATCH + TQ - 1) / TQ, NHEAD, BATCH);   // (7, 12, 8)
    attn_kernel<<<ga, 256>>>(gt);

    dim3 go(49, 6, 1);
    out_kernel<<<go, 256>>>(Wo, bo, out);
}